// round 15
// baseline (speedup 1.0000x reference)
#include <cuda_runtime.h>
#include <cuda_fp16.h>
#include <string.h>

#define NM 128
#define NM3 (NM * NM * NM)
#define NC 16
#define NPTS 100000
#define INV_SPACING 10.0f

#define T_ITERS 2048          // transpose iterations (256 quad-cells each)
#define BATCH 4               // iterations per steal
#define NBATCH (T_ITERS / BATCH)   // 512 batches
#define GRID_BLOCKS 1024
#define INTERP_BASE 633       // blocks [633, 1023] own interp (391 blocks)

// Scratch: mesh transposed to (x,y,z,c) fp16 layout. Cell = 32B.
__device__ ulonglong4 g_scratch[NM3];
// Device-side phase counters (reset by init kernel each call)
__device__ unsigned g_t_next;
__device__ unsigned g_t_done;

static __device__ __forceinline__ unsigned h2u(__half2 h) {
    unsigned u; memcpy(&u, &h, 4); return u;
}
static __device__ __forceinline__ __half2 u2h(unsigned u) {
    __half2 h; memcpy(&h, &u, 4); return h;
}
static __device__ __forceinline__ unsigned long long pack64(unsigned lo, unsigned hi) {
    return (unsigned long long)lo | ((unsigned long long)hi << 32);
}
static __device__ __forceinline__ void st_cell_evict_last(ulonglong4* p, ulonglong4 v) {
    asm volatile("st.global.L2::evict_last.v4.b64 [%0], {%1,%2,%3,%4};"
                 :: "l"(p), "l"(v.x), "l"(v.y), "l"(v.z), "l"(v.w) : "memory");
}
static __device__ __forceinline__ ulonglong4 ld_cell_nc(const ulonglong4* p) {
    ulonglong4 r;
    asm("ld.global.nc.v4.b64 {%0,%1,%2,%3}, [%4];"
        : "=l"(r.x), "=l"(r.y), "=l"(r.z), "=l"(r.w) : "l"(p));
    return r;
}

__global__ void init_kernel() {
    g_t_next = 0;
    g_t_done = 0;
}

// R9 transpose body for one quad-cell (4 consecutive z-cells).
static __device__ __forceinline__ void transpose_quadcell(
        const float* __restrict__ in, int q) {
    int cell0 = q * 4;
    float4 v[NC];
#pragma unroll
    for (int c = 0; c < NC; c++) {
        v[c] = __ldcs((const float4*)(in + (size_t)c * NM3 + cell0));
    }
#pragma unroll
    for (int z = 0; z < 4; z++) {
        float f[NC];
#pragma unroll
        for (int c = 0; c < NC; c++) {
            f[c] = (z == 0) ? v[c].x : (z == 1) ? v[c].y : (z == 2) ? v[c].z : v[c].w;
        }
        ulonglong4 cell;
        cell.x = pack64(h2u(__floats2half2_rn(f[0],  f[1])),
                        h2u(__floats2half2_rn(f[2],  f[3])));
        cell.y = pack64(h2u(__floats2half2_rn(f[4],  f[5])),
                        h2u(__floats2half2_rn(f[6],  f[7])));
        cell.z = pack64(h2u(__floats2half2_rn(f[8],  f[9])),
                        h2u(__floats2half2_rn(f[10], f[11])));
        cell.w = pack64(h2u(__floats2half2_rn(f[12], f[13])),
                        h2u(__floats2half2_rn(f[14], f[15])));
        st_cell_evict_last(&g_scratch[cell0 + z], cell);
    }
}

// R9 interp body for one point (27 independent 32B LDG.256 taps).
static __device__ __forceinline__ void interp_point(
        const float* __restrict__ points, float4* __restrict__ out, int p) {
    float px = points[p * 3 + 0] * INV_SPACING;
    float py = points[p * 3 + 1] * INV_SPACING;
    float pz = points[p * 3 + 2] * INV_SPACING;

    float rx = rintf(px), ry = rintf(py), rz = rintf(pz);
    float dx = px - rx, dy = py - ry, dz = pz - rz;
    int ix = (int)rx, iy = (int)ry, iz = (int)rz;

    float wx[3], wy[3], wz[3];
    {
        float a;
        a = 2.0f * dx - 1.0f; wx[0] = a * a * 0.125f;
        wx[1] = 0.75f - dx * dx;
        a = 2.0f * dx + 1.0f; wx[2] = a * a * 0.125f;

        a = 2.0f * dy - 1.0f; wy[0] = a * a * 0.125f;
        wy[1] = 0.75f - dy * dy;
        a = 2.0f * dy + 1.0f; wy[2] = a * a * 0.125f;

        a = 2.0f * dz - 1.0f; wz[0] = a * a * 0.125f;
        wz[1] = 0.75f - dz * dz;
        a = 2.0f * dz + 1.0f; wz[2] = a * a * 0.125f;
    }

    int xs[3], ys[3], zs[3];
    xs[0] = (ix + 127) & (NM - 1); xs[1] = ix & (NM - 1); xs[2] = (ix + 129) & (NM - 1);
    ys[0] = (iy + 127) & (NM - 1); ys[1] = iy & (NM - 1); ys[2] = (iy + 129) & (NM - 1);
    zs[0] = (iz + 127) & (NM - 1); zs[1] = iz & (NM - 1); zs[2] = (iz + 129) & (NM - 1);

    float acc[NC];
#pragma unroll
    for (int c = 0; c < NC; c++) acc[c] = 0.0f;

#pragma unroll
    for (int ox = 0; ox < 3; ox++) {
#pragma unroll
        for (int oy = 0; oy < 3; oy++) {
            float wxy = wx[ox] * wy[oy];
            int rowbase = (xs[ox] * NM + ys[oy]) * NM;
#pragma unroll
            for (int oz = 0; oz < 3; oz++) {
                float w = wxy * wz[oz];
                ulonglong4 raw = ld_cell_nc(&g_scratch[rowbase + zs[oz]]);
                unsigned long long qd[4] = {raw.x, raw.y, raw.z, raw.w};
#pragma unroll
                for (int j = 0; j < 4; j++) {
                    float2 f0 = __half22float2(u2h((unsigned)qd[j]));
                    float2 f1 = __half22float2(u2h((unsigned)(qd[j] >> 32)));
                    acc[j * 4 + 0] += w * f0.x;
                    acc[j * 4 + 1] += w * f0.y;
                    acc[j * 4 + 2] += w * f1.x;
                    acc[j * 4 + 3] += w * f1.y;
                }
            }
        }
    }

    float4* o = out + (size_t)p * 4;
    __stcs(o + 0, make_float4(acc[0],  acc[1],  acc[2],  acc[3]));
    __stcs(o + 1, make_float4(acc[4],  acc[5],  acc[6],  acc[7]));
    __stcs(o + 2, make_float4(acc[8],  acc[9],  acc[10], acc[11]));
    __stcs(o + 3, make_float4(acc[12], acc[13], acc[14], acc[15]));
}

// ---------------------------------------------------------------------------
// Fused kernel. Phase 1: all blocks work-steal transpose batches until
// exhausted (first resident wave does all of it at full width). Phase 2:
// interp-role blocks (last 391) spin on the done-counter, then interpolate
// against the scratch written in THIS launch (within-launch L2 persistence).
// Deadlock-free: every claimed batch is owned by a live resident block, so
// g_t_done always reaches NBATCH; non-interp blocks never wait.
// ---------------------------------------------------------------------------
__global__ void __launch_bounds__(256) fused_kernel(
        const float* __restrict__ mesh,
        const float* __restrict__ points,
        float4* __restrict__ out) {
    __shared__ unsigned s_b;

    // Phase 1: steal transpose batches.
    for (;;) {
        if (threadIdx.x == 0) s_b = atomicAdd(&g_t_next, 1u);
        __syncthreads();
        unsigned b = s_b;
        if (b >= NBATCH) break;
#pragma unroll
        for (int k = 0; k < BATCH; k++) {
            int q = (int)(b * BATCH + k) * 256 + threadIdx.x;
            transpose_quadcell(mesh, q);
        }
        __threadfence();          // make this block's scratch stores visible
        __syncthreads();
        if (threadIdx.x == 0) atomicAdd(&g_t_done, 1u);
    }

    // Non-interp blocks retire immediately.
    if (blockIdx.x < INTERP_BASE) return;

    // Phase 2 gate: wait until ALL transpose batches complete.
    if (threadIdx.x == 0) {
        while (atomicAdd(&g_t_done, 0u) < NBATCH) __nanosleep(512);
        __threadfence();          // acquire: order scratch reads after gate
    }
    __syncthreads();

    int p = (blockIdx.x - INTERP_BASE) * 256 + threadIdx.x;
    if (p < NPTS) interp_point(points, out, p);
}

extern "C" void kernel_launch(void* const* d_in, const int* in_sizes, int n_in,
                              void* d_out, int out_size) {
    const float* mesh = (const float*)d_in[0];    // (16, 128, 128, 128) f32
    const float* points = (const float*)d_in[1];  // (100000, 3) f32
    float4* out = (float4*)d_out;                 // (100000, 16) f32

    init_kernel<<<1, 1>>>();
    fused_kernel<<<GRID_BLOCKS, 256>>>(mesh, points, out);
}

// round 16
// speedup vs baseline: 1.1338x; 1.1338x over previous
#include <cuda_runtime.h>
#include <cuda_fp16.h>
#include <string.h>

#define NM 128
#define NM3 (NM * NM * NM)
#define NC 16
#define NPTS 100000
#define INV_SPACING 10.0f

#define T_ITERS 2048               // transpose iterations (256 quad-cells each)
#define BATCH 4                    // iterations per steal
#define NBATCH (T_ITERS / BATCH)   // 512 batches
#define GRID_BLOCKS 1024
#define INTERP_BASE 633            // blocks [633, 1023] own interp (391 blocks)

// Scratch: mesh transposed to (x,y,z,c) fp16 layout. Cell = 32B.
__device__ ulonglong4 g_scratch[NM3];
// Device-side phase counters (reset by init kernel each call)
__device__ unsigned g_t_next;
__device__ unsigned g_t_done;

static __device__ __forceinline__ unsigned h2u(__half2 h) {
    unsigned u; memcpy(&u, &h, 4); return u;
}
static __device__ __forceinline__ __half2 u2h(unsigned u) {
    __half2 h; memcpy(&h, &u, 4); return h;
}
static __device__ __forceinline__ unsigned long long pack64(unsigned lo, unsigned hi) {
    return (unsigned long long)lo | ((unsigned long long)hi << 32);
}
static __device__ __forceinline__ void st_cell_evict_last(ulonglong4* p, ulonglong4 v) {
    asm volatile("st.global.L2::evict_last.v4.b64 [%0], {%1,%2,%3,%4};"
                 :: "l"(p), "l"(v.x), "l"(v.y), "l"(v.z), "l"(v.w) : "memory");
}
static __device__ __forceinline__ ulonglong4 ld_cell_nc(const ulonglong4* p) {
    ulonglong4 r;
    asm("ld.global.nc.v4.b64 {%0,%1,%2,%3}, [%4];"
        : "=l"(r.x), "=l"(r.y), "=l"(r.z), "=l"(r.w) : "l"(p));
    return r;
}

__global__ void init_kernel() {
    g_t_next = 0;
    g_t_done = 0;
}

// R9 transpose body for one quad-cell (4 consecutive z-cells).
static __device__ __forceinline__ void transpose_quadcell(
        const float* __restrict__ in, int q) {
    int cell0 = q * 4;
    float4 v[NC];
#pragma unroll
    for (int c = 0; c < NC; c++) {
        v[c] = __ldcs((const float4*)(in + (size_t)c * NM3 + cell0));
    }
#pragma unroll
    for (int z = 0; z < 4; z++) {
        float f[NC];
#pragma unroll
        for (int c = 0; c < NC; c++) {
            f[c] = (z == 0) ? v[c].x : (z == 1) ? v[c].y : (z == 2) ? v[c].z : v[c].w;
        }
        ulonglong4 cell;
        cell.x = pack64(h2u(__floats2half2_rn(f[0],  f[1])),
                        h2u(__floats2half2_rn(f[2],  f[3])));
        cell.y = pack64(h2u(__floats2half2_rn(f[4],  f[5])),
                        h2u(__floats2half2_rn(f[6],  f[7])));
        cell.z = pack64(h2u(__floats2half2_rn(f[8],  f[9])),
                        h2u(__floats2half2_rn(f[10], f[11])));
        cell.w = pack64(h2u(__floats2half2_rn(f[12], f[13])),
                        h2u(__floats2half2_rn(f[14], f[15])));
        st_cell_evict_last(&g_scratch[cell0 + z], cell);
    }
}

// R9 interp body for one point (27 independent 32B LDG.256 taps).
static __device__ __forceinline__ void interp_point(
        const float* __restrict__ points, float4* __restrict__ out, int p) {
    float px = points[p * 3 + 0] * INV_SPACING;
    float py = points[p * 3 + 1] * INV_SPACING;
    float pz = points[p * 3 + 2] * INV_SPACING;

    float rx = rintf(px), ry = rintf(py), rz = rintf(pz);
    float dx = px - rx, dy = py - ry, dz = pz - rz;
    int ix = (int)rx, iy = (int)ry, iz = (int)rz;

    float wx[3], wy[3], wz[3];
    {
        float a;
        a = 2.0f * dx - 1.0f; wx[0] = a * a * 0.125f;
        wx[1] = 0.75f - dx * dx;
        a = 2.0f * dx + 1.0f; wx[2] = a * a * 0.125f;

        a = 2.0f * dy - 1.0f; wy[0] = a * a * 0.125f;
        wy[1] = 0.75f - dy * dy;
        a = 2.0f * dy + 1.0f; wy[2] = a * a * 0.125f;

        a = 2.0f * dz - 1.0f; wz[0] = a * a * 0.125f;
        wz[1] = 0.75f - dz * dz;
        a = 2.0f * dz + 1.0f; wz[2] = a * a * 0.125f;
    }

    int xs[3], ys[3], zs[3];
    xs[0] = (ix + 127) & (NM - 1); xs[1] = ix & (NM - 1); xs[2] = (ix + 129) & (NM - 1);
    ys[0] = (iy + 127) & (NM - 1); ys[1] = iy & (NM - 1); ys[2] = (iy + 129) & (NM - 1);
    zs[0] = (iz + 127) & (NM - 1); zs[1] = iz & (NM - 1); zs[2] = (iz + 129) & (NM - 1);

    float acc[NC];
#pragma unroll
    for (int c = 0; c < NC; c++) acc[c] = 0.0f;

#pragma unroll
    for (int ox = 0; ox < 3; ox++) {
#pragma unroll
        for (int oy = 0; oy < 3; oy++) {
            float wxy = wx[ox] * wy[oy];
            int rowbase = (xs[ox] * NM + ys[oy]) * NM;
#pragma unroll
            for (int oz = 0; oz < 3; oz++) {
                float w = wxy * wz[oz];
                ulonglong4 raw = ld_cell_nc(&g_scratch[rowbase + zs[oz]]);
                unsigned long long qd[4] = {raw.x, raw.y, raw.z, raw.w};
#pragma unroll
                for (int j = 0; j < 4; j++) {
                    float2 f0 = __half22float2(u2h((unsigned)qd[j]));
                    float2 f1 = __half22float2(u2h((unsigned)(qd[j] >> 32)));
                    acc[j * 4 + 0] += w * f0.x;
                    acc[j * 4 + 1] += w * f0.y;
                    acc[j * 4 + 2] += w * f1.x;
                    acc[j * 4 + 3] += w * f1.y;
                }
            }
        }
    }

    float4* o = out + (size_t)p * 4;
    __stcs(o + 0, make_float4(acc[0],  acc[1],  acc[2],  acc[3]));
    __stcs(o + 1, make_float4(acc[4],  acc[5],  acc[6],  acc[7]));
    __stcs(o + 2, make_float4(acc[8],  acc[9],  acc[10], acc[11]));
    __stcs(o + 3, make_float4(acc[12], acc[13], acc[14], acc[15]));
}

// ---------------------------------------------------------------------------
// Fused kernel, R16: per-BLOCK fence instead of per-batch fence.
// Phase 1: all blocks work-steal transpose batches until exhausted. Each
// block fences ONCE after its last batch, then contributes its batch count
// to g_t_done. (R15's per-batch __threadfence drained the store pipe 512
// times and serialized phase 1 — that was the regression.)
// Phase 2: interp-role blocks spin until g_t_done == NBATCH, then
// interpolate against scratch written in THIS launch.
// Deadlock-free: every claimed batch is owned by a live resident block.
// ---------------------------------------------------------------------------
__global__ void __launch_bounds__(256) fused_kernel(
        const float* __restrict__ mesh,
        const float* __restrict__ points,
        float4* __restrict__ out) {
    __shared__ unsigned s_b;
    unsigned my_batches = 0;

    // Phase 1: steal transpose batches (no per-batch fence).
    for (;;) {
        if (threadIdx.x == 0) s_b = atomicAdd(&g_t_next, 1u);
        __syncthreads();
        unsigned b = s_b;
        __syncthreads();
        if (b >= NBATCH) break;
        my_batches++;
#pragma unroll
        for (int k = 0; k < BATCH; k++) {
            int q = (int)(b * BATCH + k) * 256 + threadIdx.x;
            transpose_quadcell(mesh, q);
        }
    }

    // One fence per block: all this block's scratch stores become visible
    // before its batches are counted as done.
    __threadfence();
    __syncthreads();
    if (threadIdx.x == 0 && my_batches > 0) atomicAdd(&g_t_done, my_batches);

    // Non-interp blocks retire immediately.
    if (blockIdx.x < INTERP_BASE) return;

    // Phase 2 gate: wait until ALL transpose batches complete.
    if (threadIdx.x == 0) {
        while (atomicAdd(&g_t_done, 0u) < NBATCH) __nanosleep(256);
        __threadfence();          // acquire: order scratch reads after gate
    }
    __syncthreads();

    int p = (blockIdx.x - INTERP_BASE) * 256 + threadIdx.x;
    if (p < NPTS) interp_point(points, out, p);
}

extern "C" void kernel_launch(void* const* d_in, const int* in_sizes, int n_in,
                              void* d_out, int out_size) {
    const float* mesh = (const float*)d_in[0];    // (16, 128, 128, 128) f32
    const float* points = (const float*)d_in[1];  // (100000, 3) f32
    float4* out = (float4*)d_out;                 // (100000, 16) f32

    init_kernel<<<1, 1>>>();
    fused_kernel<<<GRID_BLOCKS, 256>>>(mesh, points, out);
}

// round 17
// speedup vs baseline: 1.2536x; 1.1057x over previous
#include <cuda_runtime.h>
#include <cuda_fp16.h>
#include <string.h>

#define NM 128
#define NM3 (NM * NM * NM)
#define NC 16
#define NPTS 100000
#define INV_SPACING 10.0f

// Scratch: mesh transposed to (x,y,z,c) fp16 layout. One cell = 32B.
__device__ ulonglong4 g_scratch[NM3];

static __device__ __forceinline__ unsigned h2u(__half2 h) {
    unsigned u; memcpy(&u, &h, 4); return u;
}
static __device__ __forceinline__ __half2 u2h(unsigned u) {
    __half2 h; memcpy(&h, &u, 4); return h;
}
static __device__ __forceinline__ unsigned long long pack64(unsigned lo, unsigned hi) {
    return (unsigned long long)lo | ((unsigned long long)hi << 32);
}
static __device__ __forceinline__ void st_cell_evict_last(ulonglong4* p, ulonglong4 v) {
    asm volatile("st.global.L2::evict_last.v4.b64 [%0], {%1,%2,%3,%4};"
                 :: "l"(p), "l"(v.x), "l"(v.y), "l"(v.z), "l"(v.w) : "memory");
}
static __device__ __forceinline__ ulonglong4 ld_cell_nc(const ulonglong4* p) {
    ulonglong4 r;
    asm("ld.global.nc.v4.b64 {%0,%1,%2,%3}, [%4];"
        : "=l"(r.x), "=l"(r.y), "=l"(r.z), "=l"(r.w) : "l"(p));
    return r;
}
static __device__ __forceinline__ float pick3f(float a0, float a1, float a2, int k) {
    return (k == 0) ? a0 : ((k == 1) ? a1 : a2);
}
static __device__ __forceinline__ int pick3i(int a0, int a1, int a2, int k) {
    return (k == 0) ? a0 : ((k == 1) ? a1 : a2);
}

// ---------------------------------------------------------------------------
// Kernel 1: transpose (c, cell)f32 -> (cell, c)f16   [at DRAM roofline, R9]
// ---------------------------------------------------------------------------
__global__ void mesh_transpose_f16_kernel(const float* __restrict__ in) {
    int q = blockIdx.x * blockDim.x + threadIdx.x;   // quad-cell index
    if (q >= NM3 / 4) return;
    int cell0 = q * 4;

    float4 v[NC];
#pragma unroll
    for (int c = 0; c < NC; c++) {
        v[c] = __ldcs((const float4*)(in + (size_t)c * NM3 + cell0));
    }

#pragma unroll
    for (int z = 0; z < 4; z++) {
        float f[NC];
#pragma unroll
        for (int c = 0; c < NC; c++) {
            f[c] = (z == 0) ? v[c].x : (z == 1) ? v[c].y : (z == 2) ? v[c].z : v[c].w;
        }
        ulonglong4 cell;
        cell.x = pack64(h2u(__floats2half2_rn(f[0],  f[1])),
                        h2u(__floats2half2_rn(f[2],  f[3])));
        cell.y = pack64(h2u(__floats2half2_rn(f[4],  f[5])),
                        h2u(__floats2half2_rn(f[6],  f[7])));
        cell.z = pack64(h2u(__floats2half2_rn(f[8],  f[9])),
                        h2u(__floats2half2_rn(f[10], f[11])));
        cell.w = pack64(h2u(__floats2half2_rn(f[12], f[13])),
                        h2u(__floats2half2_rn(f[14], f[15])));
        st_cell_evict_last(&g_scratch[cell0 + z], cell);
    }
}

// ---------------------------------------------------------------------------
// Kernel 2: TSC interpolation, 2 threads/point with ARITHMETIC tap decode.
// Lane pair (2k, 2k+1) shares point p; thread s handles taps {2i+s}.
// Since i is unrolled and s is one runtime bit, each tap's (ox,oy,oz)/weight/
// offset is a single select -> every 32B LDG.256 executes FULL-width (the
// fix for R10's half-predicated loads). 8 shfls swap channel halves; both
// lanes store 32B (fully coalesced 1KB/warp output).
// ---------------------------------------------------------------------------
__global__ void __launch_bounds__(256) interp_f16_kernel(
        const float* __restrict__ points, float4* __restrict__ out) {
    int t = blockIdx.x * blockDim.x + threadIdx.x;
    int p = t >> 1;
    int s = t & 1;
    bool valid = (p < NPTS);
    int pc = valid ? p : (NPTS - 1);   // clamp; shfl needs live partners

    float px = points[pc * 3 + 0] * INV_SPACING;
    float py = points[pc * 3 + 1] * INV_SPACING;
    float pz = points[pc * 3 + 2] * INV_SPACING;

    float rx = rintf(px), ry = rintf(py), rz = rintf(pz);
    float dx = px - rx, dy = py - ry, dz = pz - rz;
    int ix = (int)rx, iy = (int)ry, iz = (int)rz;

    float wx0, wx1, wx2, wy0, wy1, wy2, wz0, wz1, wz2;
    {
        float a;
        a = 2.0f * dx - 1.0f; wx0 = a * a * 0.125f;
        wx1 = 0.75f - dx * dx;
        a = 2.0f * dx + 1.0f; wx2 = a * a * 0.125f;

        a = 2.0f * dy - 1.0f; wy0 = a * a * 0.125f;
        wy1 = 0.75f - dy * dy;
        a = 2.0f * dy + 1.0f; wy2 = a * a * 0.125f;

        a = 2.0f * dz - 1.0f; wz0 = a * a * 0.125f;
        wz1 = 0.75f - dz * dz;
        a = 2.0f * dz + 1.0f; wz2 = a * a * 0.125f;
    }

    // Row offsets: x * NM^2, y * NM, z
    int xr0 = ((ix + 127) & (NM - 1)) * NM * NM;
    int xr1 = (ix & (NM - 1)) * NM * NM;
    int xr2 = ((ix + 129) & (NM - 1)) * NM * NM;
    int yr0 = ((iy + 127) & (NM - 1)) * NM;
    int yr1 = (iy & (NM - 1)) * NM;
    int yr2 = ((iy + 129) & (NM - 1)) * NM;
    int zr0 = (iz + 127) & (NM - 1);
    int zr1 = iz & (NM - 1);
    int zr2 = (iz + 129) & (NM - 1);

    float acc[NC];
#pragma unroll
    for (int c = 0; c < NC; c++) acc[c] = 0.0f;

#pragma unroll
    for (int i = 0; i < 14; i++) {
        int tap = 2 * i + s;                 // two possible values per i
        int tt = (tap < 27) ? tap : 26;      // i=13,s=1 -> dummy
        int ox = tt / 9;
        int rem = tt - ox * 9;
        int oy = rem / 3;
        int oz = rem - oy * 3;

        float w = pick3f(wx0, wx1, wx2, ox) *
                  pick3f(wy0, wy1, wy2, oy) *
                  pick3f(wz0, wz1, wz2, oz);
        w = (tap < 27) ? w : 0.0f;

        int cell = pick3i(xr0, xr1, xr2, ox) +
                   pick3i(yr0, yr1, yr2, oy) +
                   pick3i(zr0, zr1, zr2, oz);

        ulonglong4 raw = ld_cell_nc(&g_scratch[cell]);
        unsigned long long qd[4] = {raw.x, raw.y, raw.z, raw.w};
#pragma unroll
        for (int j = 0; j < 4; j++) {
            float2 f0 = __half22float2(u2h((unsigned)qd[j]));
            float2 f1 = __half22float2(u2h((unsigned)(qd[j] >> 32)));
            acc[j * 4 + 0] += w * f0.x;
            acc[j * 4 + 1] += w * f0.y;
            acc[j * 4 + 2] += w * f1.x;
            acc[j * 4 + 3] += w * f1.y;
        }
    }

    // Swap channel halves with partner lane: s=0 keeps ch0-7 (receives
    // partner's ch0-7 partials), s=1 keeps ch8-15.
#pragma unroll
    for (int j = 0; j < 8; j++) {
        float send = (s == 0) ? acc[8 + j] : acc[j];
        float recv = __shfl_xor_sync(0xffffffffu, send, 1);
        int mine = (s == 0) ? j : (8 + j);
        acc[mine] += recv;
    }

    if (valid) {
        // Lane s stores channels [8s, 8s+8) = 32B; warp covers 1KB contiguous.
        int base = s * 8;
        float4* o = out + (size_t)p * 4 + s * 2;
        __stcs(o + 0, make_float4(acc[base + 0], acc[base + 1],
                                  acc[base + 2], acc[base + 3]));
        __stcs(o + 1, make_float4(acc[base + 4], acc[base + 5],
                                  acc[base + 6], acc[base + 7]));
    }
}

extern "C" void kernel_launch(void* const* d_in, const int* in_sizes, int n_in,
                              void* d_out, int out_size) {
    const float* mesh = (const float*)d_in[0];    // (16, 128, 128, 128) f32
    const float* points = (const float*)d_in[1];  // (100000, 3) f32
    float4* out = (float4*)d_out;                 // (100000, 16) f32

    {
        int threads = 256;
        int blocks = (NM3 / 4 + threads - 1) / threads;
        mesh_transpose_f16_kernel<<<blocks, threads>>>(mesh);
    }
    {
        int total = NPTS * 2;
        int threads = 256;
        int blocks = (total + threads - 1) / threads;
        interp_f16_kernel<<<blocks, threads>>>(points, out);
    }
}